// round 13
// baseline (speedup 1.0000x reference)
#include <cuda_runtime.h>
#include <cstdint>

#define N_PTS   16384
#define GRIDD   32
#define CELLS   (GRIDD * GRIDD * GRIDD)
#define LOF     (-5.0f)
#define CELL    0.3125f
#define INVCELL 3.2f
#define SUBQ    4
#define BIGF    1.0e30f
#define SBLK    256

// Scratch in device globals. Invariants restored every call:
//  g_cnt == 0 at count entry (load-time zero; count's scan block restores),
//  g_bcount/g_rcount == 0 (load-time zero; last block restores).
__device__ int      g_cnt[2][CELLS];
__device__ int      g_start[2][CELLS + 8];
__device__ unsigned g_cidrank[2][N_PTS];   // (cid << 17) | rank, unsigned
__device__ float4   g_pts[2][N_PTS];       // cell-sorted: (x, y, z, |p|^2)
__device__ float    g_sq[2][N_PTS];        // sqrt(min sq dist); -1 = pending
__device__ float    g_partial[8];
__device__ int      g_bcount;
__device__ int      g_rcount;

__device__ __forceinline__ int cell_coord(float v) {
    int c = (int)((v - LOF) * INVCELL);
    return min(max(c, 0), GRIDD - 1);
}

// Counting pass; the LAST block then performs both clouds' prefix scans,
// writes g_start, and zeroes g_cnt (restoring the entry invariant).
__global__ __launch_bounds__(1024) void count_kernel(const float* __restrict__ sx,
                                                     const float* __restrict__ tg) {
    int idx = blockIdx.x * 1024 + threadIdx.x;   // 32 blocks cover 2*16384
    int cl = idx >> 14, i = idx & (N_PTS - 1);
    const float* p = cl ? tg : sx;
    float x = p[3 * i], y = p[3 * i + 1], z = p[3 * i + 2];
    int cid = (cell_coord(z) << 10) | (cell_coord(y) << 5) | cell_coord(x);
    unsigned rank = (unsigned)atomicAdd(&g_cnt[cl][cid], 1);
    g_cidrank[cl][i] = ((unsigned)cid << 17) | rank;

    __threadfence();
    __shared__ bool amLast;
    if (threadIdx.x == 0)
        amLast = (atomicAdd(&g_bcount, 1) == 31);
    __syncthreads();
    if (!amLast) return;

    // ---- dual-cloud prefix scan in the last block ----
    const int t = threadIdx.x;
    __shared__ int sh0[1024], sh1[1024];
    int4* c0 = (int4*)&g_cnt[0][0];
    int4* c1 = (int4*)&g_cnt[1][0];
    int s0 = 0, s1 = 0;
    #pragma unroll
    for (int k = 0; k < 8; k++) {
        int4 a = c0[t * 8 + k];
        int4 b = c1[t * 8 + k];
        s0 += (a.x + a.y) + (a.z + a.w);
        s1 += (b.x + b.y) + (b.z + b.w);
    }
    sh0[t] = s0; sh1[t] = s1;
    __syncthreads();
    for (int off = 1; off < 1024; off <<= 1) {   // Hillis-Steele, both clouds
        int a = (t >= off) ? sh0[t - off] : 0;
        int b = (t >= off) ? sh1[t - off] : 0;
        __syncthreads();
        sh0[t] += a; sh1[t] += b;
        __syncthreads();
    }
    int run0 = sh0[t] - s0, run1 = sh1[t] - s1;   // exclusive prefixes
    int4* s4a = (int4*)&g_start[0][0];
    int4* s4b = (int4*)&g_start[1][0];
    #pragma unroll
    for (int k = 0; k < 8; k++) {
        int4 a = c0[t * 8 + k];                   // L1 re-read (no reg spill)
        int4 b = c1[t * 8 + k];
        int4 w0, w1;
        w0.x = run0; run0 += a.x;  w0.y = run0; run0 += a.y;
        w0.z = run0; run0 += a.z;  w0.w = run0; run0 += a.w;
        w1.x = run1; run1 += b.x;  w1.y = run1; run1 += b.y;
        w1.z = run1; run1 += b.z;  w1.w = run1; run1 += b.w;
        s4a[t * 8 + k] = w0;
        s4b[t * 8 + k] = w1;
        c0[t * 8 + k] = make_int4(0, 0, 0, 0);    // restore invariant
        c1[t * 8 + k] = make_int4(0, 0, 0, 0);
    }
    if (t == 1023) {
        g_start[0][CELLS] = run0;                 // == N_PTS
        g_start[1][CELLS] = run1;
        g_bcount = 0;                             // restore invariant
    }
}

__global__ void scatter_kernel(const float* __restrict__ sx,
                               const float* __restrict__ tg) {
    int idx = blockIdx.x * blockDim.x + threadIdx.x;
    int cl = idx >> 14, i = idx & (N_PTS - 1);
    const float* p = cl ? tg : sx;
    float x = p[3 * i], y = p[3 * i + 1], z = p[3 * i + 2];
    unsigned cr = g_cidrank[cl][i];
    int pos = g_start[cl][cr >> 17] + (int)(cr & 0x1FFFFu);
    g_pts[cl][pos] = make_float4(x, y, z, x * x + y * y + z * z);
}

// One query per 4-thread quad; branch-free 3x3x3 scan with tight slab bound.
// Unresolved queries get a -1 sentinel; the reduce kernel finishes them.
__global__ __launch_bounds__(SBLK, 4) void search_fast() {
    const int gtid = blockIdx.x * SBLK + threadIdx.x;
    const int qcl = blockIdx.y;
    const int rcl = qcl ^ 1;
    const int qid = gtid >> 2;
    const int sub = gtid & 3;
    const unsigned qmask = 0xFu << (threadIdx.x & 28);

    const float4 q = g_pts[qcl][qid];
    const float nax = -2.0f * q.x, nay = -2.0f * q.y, naz = -2.0f * q.z;
    const int cx = cell_coord(q.x), cy = cell_coord(q.y), cz = cell_coord(q.z);

    const float4* __restrict__ ref = g_pts[rcl];
    const int* __restrict__ st = g_start[rcl];

    const int xlo = max(cx - 1, 0), xhi = min(cx + 1, GRIDD - 1);
    const int ylo = max(cy - 1, 0), yhi = min(cy + 1, GRIDD - 1);
    const int zlo = max(cz - 1, 0), zhi = min(cz + 1, GRIDD - 1);
    int zr[3] = {zlo, cz, zhi};
    int yr[3] = {ylo, cy, yhi};

    int s9[9], e9[9];
    #pragma unroll
    for (int i = 0; i < 9; i++) {
        int row = (zr[i / 3] << 10) | (yr[i % 3] << 5);
        s9[i] = st[row + xlo];
        e9[i] = st[row + xhi + 1];
    }

    float m = BIGF * BIGF;   // +inf
    #pragma unroll
    for (int i = 0; i < 9; i++) {
        int p = s9[i] + sub;
        const int e = e9[i];
        for (; p + SUBQ < e; p += 2 * SUBQ) {
            float4 t0 = ref[p];
            float4 t1 = ref[p + SUBQ];
            float d0 = fmaf(nax, t0.x, fmaf(nay, t0.y, fmaf(naz, t0.z, t0.w)));
            float d1 = fmaf(nax, t1.x, fmaf(nay, t1.y, fmaf(naz, t1.z, t1.w)));
            m = fminf(m, fminf(d0, d1));
        }
        if (p < e) {
            float4 t = ref[p];
            m = fminf(m, fmaf(nax, t.x, fmaf(nay, t.y, fmaf(naz, t.z, t.w))));
        }
    }
    m = fminf(m, __shfl_xor_sync(qmask, m, 1));
    m = fminf(m, __shfl_xor_sync(qmask, m, 2));

    if (sub == 0) {
        float best = fmaxf(q.w + m, 0.0f);
        // Tight bound: distance from query to each scanned-slab face.
        // Grid-edge faces infinite (clamped points bin inside the grid).
        float bnd = BIGF;
        if (xlo > 0)        bnd = fminf(bnd, q.x - (LOF + (float)xlo * CELL));
        if (xhi < GRIDD-1)  bnd = fminf(bnd, (LOF + (float)(xhi+1) * CELL) - q.x);
        if (ylo > 0)        bnd = fminf(bnd, q.y - (LOF + (float)ylo * CELL));
        if (yhi < GRIDD-1)  bnd = fminf(bnd, (LOF + (float)(yhi+1) * CELL) - q.y);
        if (zlo > 0)        bnd = fminf(bnd, q.z - (LOF + (float)zlo * CELL));
        if (zhi < GRIDD-1)  bnd = fminf(bnd, (LOF + (float)(zhi+1) * CELL) - q.z);

        g_sq[qcl][qid] = (best <= bnd * bnd) ? sqrtf(best) : -1.0f;
    }
}

// Per block: finish the pending (-1) queries inside this block's own slice
// via warp-cooperative bounded two-phase scans, then tree-sum the slice;
// last block finalizes. No cross-block dependency for the pending work.
__global__ __launch_bounds__(1024) void reduce_kernel(float* __restrict__ out) {
    __shared__ int   plist[4096];
    __shared__ int   pcnt;
    __shared__ float red[1024];
    const int tid = threadIdx.x;
    const int wid = tid >> 5;
    const int lane = tid & 31;
    const int base = blockIdx.x * 4096;          // flat g_sq slice
    float* sq = (float*)g_sq;

    if (tid == 0) pcnt = 0;
    __syncthreads();

    // collect pending indices in this slice
    const float4* v = (const float4*)g_sq;
    float4 t = v[blockIdx.x * 1024 + tid];
    if (t.x < 0.0f) plist[atomicAdd(&pcnt, 1)] = base + tid * 4 + 0;
    if (t.y < 0.0f) plist[atomicAdd(&pcnt, 1)] = base + tid * 4 + 1;
    if (t.z < 0.0f) plist[atomicAdd(&pcnt, 1)] = base + tid * 4 + 2;
    if (t.w < 0.0f) plist[atomicAdd(&pcnt, 1)] = base + tid * 4 + 3;
    __syncthreads();

    // solve them: one warp per pending query (32 warps round-robin)
    for (int k = wid; k < pcnt; k += 32) {
        const int flat = plist[k];
        const int qcl = flat >> 14;
        const int qid = flat & (N_PTS - 1);
        const int rcl = qcl ^ 1;
        const float4* __restrict__ ref = g_pts[rcl];
        const int* __restrict__ st = g_start[rcl];
        const float4 q = g_pts[qcl][qid];
        const float bax = -2.0f * q.x, bay = -2.0f * q.y, baz = -2.0f * q.z;
        const int bcx = cell_coord(q.x), bcy = cell_coord(q.y),
                  bcz = cell_coord(q.z);
        float mm = BIGF * BIGF;

        // Phase 1: expand cube radius until ANY point is seen.
        for (int r = 1; mm >= BIGF && r <= GRIDD; r++) {
            int x0 = max(bcx - r, 0), x1 = min(bcx + r, GRIDD - 1);
            int y0 = max(bcy - r, 0), y1 = min(bcy + r, GRIDD - 1);
            int z0 = max(bcz - r, 0), z1 = min(bcz + r, GRIDD - 1);
            int ny = y1 - y0 + 1;
            int nrows = (z1 - z0 + 1) * ny;
            for (int rr = lane; rr < nrows; rr += 32) {
                int zz = z0 + rr / ny;
                int yy = y0 + rr % ny;
                int row = (zz << 10) | (yy << 5);
                int s = st[row + x0], e = st[row + x1 + 1];
                for (int p = s; p < e; p++) {
                    float4 tt = ref[p];
                    mm = fminf(mm, fmaf(bax, tt.x,
                               fmaf(bay, tt.y, fmaf(baz, tt.z, tt.w))));
                }
            }
            #pragma unroll
            for (int o = 16; o; o >>= 1)
                mm = fminf(mm, __shfl_xor_sync(0xFFFFFFFFu, mm, o));
        }

        // Phase 2: one bounded pass; unscanned cells >= R*CELL >= dub away.
        float dub = sqrtf(fmaxf(q.w + mm, 0.0f));
        int R = min((int)ceilf(dub * INVCELL), GRIDD);
        {
            int x0 = max(bcx - R, 0), x1 = min(bcx + R, GRIDD - 1);
            int y0 = max(bcy - R, 0), y1 = min(bcy + R, GRIDD - 1);
            int z0 = max(bcz - R, 0), z1 = min(bcz + R, GRIDD - 1);
            int ny = y1 - y0 + 1;
            int nrows = (z1 - z0 + 1) * ny;
            for (int rr = lane; rr < nrows; rr += 32) {
                int zz = z0 + rr / ny;
                int yy = y0 + rr % ny;
                int row = (zz << 10) | (yy << 5);
                int s = st[row + x0], e = st[row + x1 + 1];
                for (int p = s; p < e; p++) {
                    float4 tt = ref[p];
                    mm = fminf(mm, fmaf(bax, tt.x,
                               fmaf(bay, tt.y, fmaf(baz, tt.z, tt.w))));
                }
            }
            #pragma unroll
            for (int o = 16; o; o >>= 1)
                mm = fminf(mm, __shfl_xor_sync(0xFFFFFFFFu, mm, o));
        }
        if (lane == 0)
            sq[flat] = sqrtf(fmaxf(q.w + mm, 0.0f));
    }
    __syncthreads();

    // reload (same SM, post-barrier: solved values visible) and tree-sum
    float4 t2 = v[blockIdx.x * 1024 + tid];
    red[tid] = (t2.x + t2.y) + (t2.z + t2.w);
    __syncthreads();
    #pragma unroll
    for (int off = 512; off > 0; off >>= 1) {
        if (tid < off) red[tid] += red[tid + off];
        __syncthreads();
    }
    if (tid == 0) {
        g_partial[blockIdx.x] = red[0];
        __threadfence();
        if (atomicAdd(&g_rcount, 1) == 7) {       // last block finishes
            float s = 0.0f;
            volatile float* gp = g_partial;
            #pragma unroll
            for (int i = 0; i < 8; i++) s += gp[i];  // fixed order
            out[0] = s * (5.0f / (float)N_PTS);   // (mean1 + mean2)*0.5*10
            g_rcount = 0;                          // restore invariant
        }
    }
}

extern "C" void kernel_launch(void* const* d_in, const int* in_sizes, int n_in,
                              void* d_out, int out_size) {
    const float* state_x = (const float*)d_in[0];
    const float* target  = (const float*)d_in[1];

    count_kernel<<<32, 1024>>>(state_x, target);
    scatter_kernel<<<(2 * N_PTS) / 256, 256>>>(state_x, target);

    dim3 fgrid((N_PTS * SUBQ) / SBLK, 2);
    search_fast<<<fgrid, SBLK>>>();

    reduce_kernel<<<8, 1024>>>((float*)d_out);
}

// round 14
// speedup vs baseline: 1.0931x; 1.0931x over previous
#include <cuda_runtime.h>
#include <cstdint>

#define N_PTS   16384
#define GRIDD   32
#define CELLS   (GRIDD * GRIDD * GRIDD)
#define LOF     (-5.0f)
#define CELL    0.3125f
#define INVCELL 3.2f
#define SUBQ    4
#define BIGF    1.0e30f
#define SBLK    256

// Scratch in device globals. Invariants restored every call:
//  g_cnt == 0 at count entry (load-time zero; scan phase restores),
//  g_bcount/g_rcount == 0 (load-time zero; last block restores).
__device__ int      g_cnt[2][CELLS];
__device__ int      g_start[2][CELLS + 8];
__device__ unsigned g_cidrank[2][N_PTS];   // (cid << 17) | rank, unsigned
__device__ float4   g_pts[2][N_PTS];       // cell-sorted: (x, y, z, |p|^2)
__device__ float    g_sq[2][N_PTS];        // sqrt(min sq dist) per query
__device__ float    g_partial[8];
__device__ int      g_bcount;
__device__ int      g_rcount;

__device__ __forceinline__ int cell_coord(float v) {
    int c = (int)((v - LOF) * INVCELL);
    return min(max(c, 0), GRIDD - 1);
}

// Counting pass; LAST block then performs both clouds' prefix scans,
// writes g_start, zeroes g_cnt. Counts are written with atomics (L2-
// coherent) and L1D is flushed per launch, so the scan block's plain
// loads observe them; only the block-arrival counter needs ordering.
__global__ __launch_bounds__(1024) void count_scan_kernel(
        const float* __restrict__ sx, const float* __restrict__ tg) {
    int idx = blockIdx.x * 1024 + threadIdx.x;   // 32 blocks cover 2*16384
    int cl = idx >> 14, i = idx & (N_PTS - 1);
    const float* p = cl ? tg : sx;
    float x = p[3 * i], y = p[3 * i + 1], z = p[3 * i + 2];
    int cid = (cell_coord(z) << 10) | (cell_coord(y) << 5) | cell_coord(x);
    unsigned rank = (unsigned)atomicAdd(&g_cnt[cl][cid], 1);
    g_cidrank[cl][i] = ((unsigned)cid << 17) | rank;

    __shared__ bool amLast;
    __syncthreads();                      // all block's atomics issued
    if (threadIdx.x == 0) {
        __threadfence();                  // order before arrival counter
        amLast = (atomicAdd(&g_bcount, 1) == 31);
    }
    __syncthreads();
    if (!amLast) return;

    // ---- dual-cloud prefix scan in the last block ----
    const int t = threadIdx.x;
    __shared__ int sh0[1024], sh1[1024];
    int4* c0 = (int4*)&g_cnt[0][0];
    int4* c1 = (int4*)&g_cnt[1][0];
    int s0 = 0, s1 = 0;
    #pragma unroll
    for (int k = 0; k < 8; k++) {
        int4 a = c0[t * 8 + k];
        int4 b = c1[t * 8 + k];
        s0 += (a.x + a.y) + (a.z + a.w);
        s1 += (b.x + b.y) + (b.z + b.w);
    }
    sh0[t] = s0; sh1[t] = s1;
    __syncthreads();
    for (int off = 1; off < 1024; off <<= 1) {   // Hillis-Steele, both clouds
        int a = (t >= off) ? sh0[t - off] : 0;
        int b = (t >= off) ? sh1[t - off] : 0;
        __syncthreads();
        sh0[t] += a; sh1[t] += b;
        __syncthreads();
    }
    int run0 = sh0[t] - s0, run1 = sh1[t] - s1;   // exclusive prefixes
    int4* s4a = (int4*)&g_start[0][0];
    int4* s4b = (int4*)&g_start[1][0];
    #pragma unroll
    for (int k = 0; k < 8; k++) {
        int4 a = c0[t * 8 + k];                   // L1 re-read
        int4 b = c1[t * 8 + k];
        int4 w0, w1;
        w0.x = run0; run0 += a.x;  w0.y = run0; run0 += a.y;
        w0.z = run0; run0 += a.z;  w0.w = run0; run0 += a.w;
        w1.x = run1; run1 += b.x;  w1.y = run1; run1 += b.y;
        w1.z = run1; run1 += b.z;  w1.w = run1; run1 += b.w;
        s4a[t * 8 + k] = w0;
        s4b[t * 8 + k] = w1;
        c0[t * 8 + k] = make_int4(0, 0, 0, 0);    // restore invariant
        c1[t * 8 + k] = make_int4(0, 0, 0, 0);
    }
    if (t == 1023) {
        g_start[0][CELLS] = run0;                 // == N_PTS
        g_start[1][CELLS] = run1;
        g_bcount = 0;                             // restore invariant
    }
}

__global__ void scatter_kernel(const float* __restrict__ sx,
                               const float* __restrict__ tg) {
    int idx = blockIdx.x * blockDim.x + threadIdx.x;
    int cl = idx >> 14, i = idx & (N_PTS - 1);
    const float* p = cl ? tg : sx;
    float x = p[3 * i], y = p[3 * i + 1], z = p[3 * i + 2];
    unsigned cr = g_cidrank[cl][i];
    int pos = g_start[cl][cr >> 17] + (int)(cr & 0x1FFFFu);
    g_pts[cl][pos] = make_float4(x, y, z, x * x + y * y + z * z);
}

// One query per 4-thread quad; branch-free 3x3x3 fast path with a tight
// geometric bound; rare unresolved queries finished by the whole warp with
// a bounded two-phase scan (phase 1 usually skipped: m seed is finite).
__global__ __launch_bounds__(SBLK, 4) void search_kernel() {
    const int gtid = blockIdx.x * SBLK + threadIdx.x;
    const int qcl = blockIdx.y;
    const int rcl = qcl ^ 1;
    const int qid = gtid >> 2;
    const int sub = gtid & 3;
    const int lane = threadIdx.x & 31;
    const unsigned qmask = 0xFu << (threadIdx.x & 28);

    const float4 q = g_pts[qcl][qid];
    const float nax = -2.0f * q.x, nay = -2.0f * q.y, naz = -2.0f * q.z;
    const int cx = cell_coord(q.x), cy = cell_coord(q.y), cz = cell_coord(q.z);

    const float4* __restrict__ ref = g_pts[rcl];
    const int* __restrict__ st = g_start[rcl];

    const int xlo = max(cx - 1, 0), xhi = min(cx + 1, GRIDD - 1);
    const int ylo = max(cy - 1, 0), yhi = min(cy + 1, GRIDD - 1);
    const int zlo = max(cz - 1, 0), zhi = min(cz + 1, GRIDD - 1);
    int zr[3] = {zlo, cz, zhi};
    int yr[3] = {ylo, cy, yhi};

    int s9[9], e9[9];
    #pragma unroll
    for (int i = 0; i < 9; i++) {
        int row = (zr[i / 3] << 10) | (yr[i % 3] << 5);
        s9[i] = st[row + xlo];
        e9[i] = st[row + xhi + 1];
    }

    float m = BIGF * BIGF;   // +inf
    #pragma unroll
    for (int i = 0; i < 9; i++) {
        int p = s9[i] + sub;
        const int e = e9[i];
        for (; p + SUBQ < e; p += 2 * SUBQ) {
            float4 t0 = ref[p];
            float4 t1 = ref[p + SUBQ];
            float d0 = fmaf(nax, t0.x, fmaf(nay, t0.y, fmaf(naz, t0.z, t0.w)));
            float d1 = fmaf(nax, t1.x, fmaf(nay, t1.y, fmaf(naz, t1.z, t1.w)));
            m = fminf(m, fminf(d0, d1));
        }
        if (p < e) {
            float4 t = ref[p];
            m = fminf(m, fmaf(nax, t.x, fmaf(nay, t.y, fmaf(naz, t.z, t.w))));
        }
    }
    m = fminf(m, __shfl_xor_sync(qmask, m, 1));
    m = fminf(m, __shfl_xor_sync(qmask, m, 2));
    float best = fmaxf(q.w + m, 0.0f);

    // Tight bound: true distance from query to each scanned-slab face.
    // Grid-edge faces are infinite (clamped points bin inside the grid).
    float bnd = BIGF;
    if (xlo > 0)        bnd = fminf(bnd, q.x - (LOF + (float)xlo * CELL));
    if (xhi < GRIDD-1)  bnd = fminf(bnd, (LOF + (float)(xhi+1) * CELL) - q.x);
    if (ylo > 0)        bnd = fminf(bnd, q.y - (LOF + (float)ylo * CELL));
    if (yhi < GRIDD-1)  bnd = fminf(bnd, (LOF + (float)(yhi+1) * CELL) - q.y);
    if (zlo > 0)        bnd = fminf(bnd, q.z - (LOF + (float)zlo * CELL));
    if (zhi < GRIDD-1)  bnd = fminf(bnd, (LOF + (float)(zhi+1) * CELL) - q.z);

    bool unresolved = best > bnd * bnd;
    unsigned pmask = __ballot_sync(0xFFFFFFFFu, unresolved && sub == 0);
    if (sub == 0 && !unresolved) g_sq[qcl][qid] = sqrtf(best);

    // ---- rare path: whole warp finishes each pending query together ----
    while (pmask) {
        const int src = __ffs(pmask) - 1;
        pmask &= pmask - 1;
        const float bqx = __shfl_sync(0xFFFFFFFFu, q.x, src);
        const float bqy = __shfl_sync(0xFFFFFFFFu, q.y, src);
        const float bqz = __shfl_sync(0xFFFFFFFFu, q.z, src);
        const float bqw = __shfl_sync(0xFFFFFFFFu, q.w, src);
        float mm = __shfl_sync(0xFFFFFFFFu, m, src);
        const float bax = -2.0f * bqx, bay = -2.0f * bqy, baz = -2.0f * bqz;
        const int bcx = cell_coord(bqx), bcy = cell_coord(bqy),
                  bcz = cell_coord(bqz);

        // Phase 1 (usually skipped: mm finite from fast path).
        for (int r = 2; mm >= BIGF && r <= GRIDD; r++) {
            int x0 = max(bcx - r, 0), x1 = min(bcx + r, GRIDD - 1);
            int y0 = max(bcy - r, 0), y1 = min(bcy + r, GRIDD - 1);
            int z0 = max(bcz - r, 0), z1 = min(bcz + r, GRIDD - 1);
            int ny = y1 - y0 + 1;
            int nrows = (z1 - z0 + 1) * ny;
            for (int rr = lane; rr < nrows; rr += 32) {
                int zz = z0 + rr / ny;
                int yy = y0 + rr % ny;
                int row = (zz << 10) | (yy << 5);
                int s = st[row + x0], e = st[row + x1 + 1];
                for (int p = s; p < e; p++) {
                    float4 t = ref[p];
                    mm = fminf(mm, fmaf(bax, t.x,
                               fmaf(bay, t.y, fmaf(baz, t.z, t.w))));
                }
            }
            #pragma unroll
            for (int o = 16; o; o >>= 1)
                mm = fminf(mm, __shfl_xor_sync(0xFFFFFFFFu, mm, o));
        }

        // Phase 2: one bounded cube pass of radius R = ceil(dub/CELL).
        float dub = sqrtf(fmaxf(bqw + mm, 0.0f));
        int R = min((int)ceilf(dub * INVCELL), GRIDD);
        {
            int x0 = max(bcx - R, 0), x1 = min(bcx + R, GRIDD - 1);
            int y0 = max(bcy - R, 0), y1 = min(bcy + R, GRIDD - 1);
            int z0 = max(bcz - R, 0), z1 = min(bcz + R, GRIDD - 1);
            int ny = y1 - y0 + 1;
            int nrows = (z1 - z0 + 1) * ny;
            for (int rr = lane; rr < nrows; rr += 32) {
                int zz = z0 + rr / ny;
                int yy = y0 + rr % ny;
                int row = (zz << 10) | (yy << 5);
                int s = st[row + x0], e = st[row + x1 + 1];
                for (int p = s; p < e; p++) {
                    float4 t = ref[p];
                    mm = fminf(mm, fmaf(bax, t.x,
                               fmaf(bay, t.y, fmaf(baz, t.z, t.w))));
                }
            }
            #pragma unroll
            for (int o = 16; o; o >>= 1)
                mm = fminf(mm, __shfl_xor_sync(0xFFFFFFFFu, mm, o));
        }
        if (lane == src) g_sq[qcl][qid] = sqrtf(fmaxf(bqw + mm, 0.0f));
    }
}

__global__ __launch_bounds__(1024) void reduce_kernel(float* __restrict__ out) {
    __shared__ float red[1024];
    const int tid = threadIdx.x;
    const float4* v = (const float4*)g_sq;        // 8192 float4 total
    float4 t = v[blockIdx.x * 1024 + tid];
    red[tid] = (t.x + t.y) + (t.z + t.w);
    __syncthreads();
    #pragma unroll
    for (int off = 512; off > 0; off >>= 1) {
        if (tid < off) red[tid] += red[tid + off];
        __syncthreads();
    }
    if (tid == 0) {
        g_partial[blockIdx.x] = red[0];
        __threadfence();
        if (atomicAdd(&g_rcount, 1) == 7) {       // last block finishes
            float s = 0.0f;
            volatile float* gp = g_partial;
            #pragma unroll
            for (int i = 0; i < 8; i++) s += gp[i];  // fixed order
            out[0] = s * (5.0f / (float)N_PTS);   // (mean1 + mean2)*0.5*10
            g_rcount = 0;                          // restore invariant
        }
    }
}

extern "C" void kernel_launch(void* const* d_in, const int* in_sizes, int n_in,
                              void* d_out, int out_size) {
    const float* state_x = (const float*)d_in[0];
    const float* target  = (const float*)d_in[1];

    count_scan_kernel<<<32, 1024>>>(state_x, target);
    scatter_kernel<<<(2 * N_PTS) / 256, 256>>>(state_x, target);

    dim3 sgrid((N_PTS * SUBQ) / SBLK, 2);
    search_kernel<<<sgrid, SBLK>>>();

    reduce_kernel<<<8, 1024>>>((float*)d_out);
}

// round 15
// speedup vs baseline: 1.6952x; 1.5508x over previous
#include <cuda_runtime.h>
#include <cstdint>

#define N_PTS   16384
#define GRIDD   32
#define CELLS   (GRIDD * GRIDD * GRIDD)
#define LOF     (-5.0f)
#define CELL    0.3125f
#define INVCELL 3.2f
#define SUBQ    4
#define BIGF    1.0e30f
#define SBLK    256

// Scratch in device globals. Invariants restored every call:
//  g_cnt == 0 at count_kernel entry (load-time zero; scan restores),
//  g_rcount == 0 at reduce entry (load-time zero; last block restores).
__device__ int      g_cnt[2][CELLS];
__device__ int      g_start[2][CELLS + 8];
__device__ unsigned g_cidrank[2][N_PTS];   // (cid << 17) | rank, unsigned
__device__ float4   g_pts[2][N_PTS];       // cell-sorted: (x, y, z, |p|^2)
__device__ float    g_sq[2][N_PTS];        // sqrt(min sq dist) per query
__device__ float    g_partial[8];
__device__ int      g_rcount;

__device__ __forceinline__ int cell_coord(float v) {
    int c = (int)((v - LOF) * INVCELL);
    return min(max(c, 0), GRIDD - 1);
}

__global__ void count_kernel(const float* __restrict__ sx,
                             const float* __restrict__ tg) {
    int idx = blockIdx.x * blockDim.x + threadIdx.x;
    int cl = idx >> 14, i = idx & (N_PTS - 1);
    const float* p = cl ? tg : sx;
    float x = p[3 * i], y = p[3 * i + 1], z = p[3 * i + 2];
    int cid = (cell_coord(z) << 10) | (cell_coord(y) << 5) | cell_coord(x);
    unsigned rank = (unsigned)atomicAdd(&g_cnt[cl][cid], 1);
    g_cidrank[cl][i] = ((unsigned)cid << 17) | rank;
}

__global__ __launch_bounds__(1024) void scan_kernel() {
    __shared__ int sh[1024];
    const int cl = blockIdx.x;
    const int t = threadIdx.x;
    int4* c4 = (int4*)&g_cnt[cl][0];
    int loc[32];
    int sum = 0;
    #pragma unroll
    for (int k = 0; k < 8; k++) {
        int4 v = c4[t * 8 + k];
        loc[4*k+0] = v.x; loc[4*k+1] = v.y; loc[4*k+2] = v.z; loc[4*k+3] = v.w;
        sum += (v.x + v.y) + (v.z + v.w);
        c4[t * 8 + k] = make_int4(0, 0, 0, 0);   // restore invariant
    }
    sh[t] = sum;
    __syncthreads();
    for (int off = 1; off < 1024; off <<= 1) {   // Hillis-Steele inclusive
        int v = (t >= off) ? sh[t - off] : 0;
        __syncthreads();
        sh[t] += v;
        __syncthreads();
    }
    int run = sh[t] - sum;                        // exclusive prefix
    int4* s4 = (int4*)&g_start[cl][0];
    #pragma unroll
    for (int k = 0; k < 8; k++) {
        int4 w;
        w.x = run; run += loc[4*k+0];
        w.y = run; run += loc[4*k+1];
        w.z = run; run += loc[4*k+2];
        w.w = run; run += loc[4*k+3];
        s4[t * 8 + k] = w;
    }
    if (t == 1023) g_start[cl][CELLS] = run;      // == N_PTS
}

__global__ void scatter_kernel(const float* __restrict__ sx,
                               const float* __restrict__ tg) {
    int idx = blockIdx.x * blockDim.x + threadIdx.x;
    int cl = idx >> 14, i = idx & (N_PTS - 1);
    const float* p = cl ? tg : sx;
    float x = p[3 * i], y = p[3 * i + 1], z = p[3 * i + 2];
    unsigned cr = g_cidrank[cl][i];
    int pos = g_start[cl][cr >> 17] + (int)(cr & 0x1FFFFu);
    g_pts[cl][pos] = make_float4(x, y, z, x * x + y * y + z * z);
}

// One query per 4-thread quad; branch-free 3x3x3 fast path (unroll x4 for
// MLP=4 — the kernel is exposed-latency bound, not work bound); rare
// unresolved queries finished warp-cooperatively with a bounded two-phase
// scan seeded by the fast path's finite min (phase 1 almost always skipped).
__global__ __launch_bounds__(SBLK, 4) void search_kernel() {
    const int gtid = blockIdx.x * SBLK + threadIdx.x;
    const int qcl = blockIdx.y;
    const int rcl = qcl ^ 1;
    const int qid = gtid >> 2;
    const int sub = gtid & 3;
    const int lane = threadIdx.x & 31;
    const unsigned qmask = 0xFu << (threadIdx.x & 28);

    const float4 q = g_pts[qcl][qid];
    const float nax = -2.0f * q.x, nay = -2.0f * q.y, naz = -2.0f * q.z;
    const int cx = cell_coord(q.x), cy = cell_coord(q.y), cz = cell_coord(q.z);

    const float4* __restrict__ ref = g_pts[rcl];
    const int* __restrict__ st = g_start[rcl];

    const int xlo = max(cx - 1, 0), xhi = min(cx + 1, GRIDD - 1);
    const int ylo = max(cy - 1, 0), yhi = min(cy + 1, GRIDD - 1);
    const int zlo = max(cz - 1, 0), zhi = min(cz + 1, GRIDD - 1);
    int zr[3] = {zlo, cz, zhi};
    int yr[3] = {ylo, cy, yhi};

    int s9[9], e9[9];
    #pragma unroll
    for (int i = 0; i < 9; i++) {
        int row = (zr[i / 3] << 10) | (yr[i % 3] << 5);
        s9[i] = st[row + xlo];
        e9[i] = st[row + xhi + 1];
    }

    float m = BIGF * BIGF;   // +inf
    #pragma unroll
    for (int i = 0; i < 9; i++) {
        int p = s9[i] + sub;
        const int e = e9[i];
        // unroll x4: 4 independent loads in flight (MLP=4)
        for (; p + 3 * SUBQ < e; p += 4 * SUBQ) {
            float4 t0 = ref[p];
            float4 t1 = ref[p + SUBQ];
            float4 t2 = ref[p + 2 * SUBQ];
            float4 t3 = ref[p + 3 * SUBQ];
            float d0 = fmaf(nax, t0.x, fmaf(nay, t0.y, fmaf(naz, t0.z, t0.w)));
            float d1 = fmaf(nax, t1.x, fmaf(nay, t1.y, fmaf(naz, t1.z, t1.w)));
            float d2 = fmaf(nax, t2.x, fmaf(nay, t2.y, fmaf(naz, t2.z, t2.w)));
            float d3 = fmaf(nax, t3.x, fmaf(nay, t3.y, fmaf(naz, t3.z, t3.w)));
            m = fminf(m, fminf(fminf(d0, d1), fminf(d2, d3)));
        }
        // cleanup (<= 3 points)
        for (; p < e; p += SUBQ) {
            float4 t = ref[p];
            m = fminf(m, fmaf(nax, t.x, fmaf(nay, t.y, fmaf(naz, t.z, t.w))));
        }
    }
    m = fminf(m, __shfl_xor_sync(qmask, m, 1));
    m = fminf(m, __shfl_xor_sync(qmask, m, 2));
    float best = fmaxf(q.w + m, 0.0f);

    // Tight bound: true distance from query to each scanned-slab face.
    // Grid-edge faces are infinite (clamped points bin inside the grid).
    float bnd = BIGF;
    if (xlo > 0)        bnd = fminf(bnd, q.x - (LOF + (float)xlo * CELL));
    if (xhi < GRIDD-1)  bnd = fminf(bnd, (LOF + (float)(xhi+1) * CELL) - q.x);
    if (ylo > 0)        bnd = fminf(bnd, q.y - (LOF + (float)ylo * CELL));
    if (yhi < GRIDD-1)  bnd = fminf(bnd, (LOF + (float)(yhi+1) * CELL) - q.y);
    if (zlo > 0)        bnd = fminf(bnd, q.z - (LOF + (float)zlo * CELL));
    if (zhi < GRIDD-1)  bnd = fminf(bnd, (LOF + (float)(zhi+1) * CELL) - q.z);

    bool unresolved = best > bnd * bnd;
    unsigned pmask = __ballot_sync(0xFFFFFFFFu, unresolved && sub == 0);
    if (sub == 0 && !unresolved) g_sq[qcl][qid] = sqrtf(best);

    // ---- rare path: whole warp finishes each pending query together ----
    while (pmask) {
        const int src = __ffs(pmask) - 1;
        pmask &= pmask - 1;
        const float bqx = __shfl_sync(0xFFFFFFFFu, q.x, src);
        const float bqy = __shfl_sync(0xFFFFFFFFu, q.y, src);
        const float bqz = __shfl_sync(0xFFFFFFFFu, q.z, src);
        const float bqw = __shfl_sync(0xFFFFFFFFu, q.w, src);
        float mm = __shfl_sync(0xFFFFFFFFu, m, src);
        const float bax = -2.0f * bqx, bay = -2.0f * bqy, baz = -2.0f * bqz;
        const int bcx = cell_coord(bqx), bcy = cell_coord(bqy),
                  bcz = cell_coord(bqz);

        // Phase 1 (usually skipped: mm finite from fast path).
        for (int r = 2; mm >= BIGF && r <= GRIDD; r++) {
            int x0 = max(bcx - r, 0), x1 = min(bcx + r, GRIDD - 1);
            int y0 = max(bcy - r, 0), y1 = min(bcy + r, GRIDD - 1);
            int z0 = max(bcz - r, 0), z1 = min(bcz + r, GRIDD - 1);
            int ny = y1 - y0 + 1;
            int nrows = (z1 - z0 + 1) * ny;
            for (int rr = lane; rr < nrows; rr += 32) {
                int zz = z0 + rr / ny;
                int yy = y0 + rr % ny;
                int row = (zz << 10) | (yy << 5);
                int s = st[row + x0], e = st[row + x1 + 1];
                for (int p = s; p < e; p++) {
                    float4 t = ref[p];
                    mm = fminf(mm, fmaf(bax, t.x,
                               fmaf(bay, t.y, fmaf(baz, t.z, t.w))));
                }
            }
            #pragma unroll
            for (int o = 16; o; o >>= 1)
                mm = fminf(mm, __shfl_xor_sync(0xFFFFFFFFu, mm, o));
        }

        // Phase 2: one bounded cube pass of radius R = ceil(dub/CELL).
        float dub = sqrtf(fmaxf(bqw + mm, 0.0f));
        int R = min((int)ceilf(dub * INVCELL), GRIDD);
        {
            int x0 = max(bcx - R, 0), x1 = min(bcx + R, GRIDD - 1);
            int y0 = max(bcy - R, 0), y1 = min(bcy + R, GRIDD - 1);
            int z0 = max(bcz - R, 0), z1 = min(bcz + R, GRIDD - 1);
            int ny = y1 - y0 + 1;
            int nrows = (z1 - z0 + 1) * ny;
            for (int rr = lane; rr < nrows; rr += 32) {
                int zz = z0 + rr / ny;
                int yy = y0 + rr % ny;
                int row = (zz << 10) | (yy << 5);
                int s = st[row + x0], e = st[row + x1 + 1];
                for (int p = s; p < e; p++) {
                    float4 t = ref[p];
                    mm = fminf(mm, fmaf(bax, t.x,
                               fmaf(bay, t.y, fmaf(baz, t.z, t.w))));
                }
            }
            #pragma unroll
            for (int o = 16; o; o >>= 1)
                mm = fminf(mm, __shfl_xor_sync(0xFFFFFFFFu, mm, o));
        }
        if (lane == src) g_sq[qcl][qid] = sqrtf(fmaxf(bqw + mm, 0.0f));
    }
}

__global__ __launch_bounds__(1024) void reduce_kernel(float* __restrict__ out) {
    __shared__ float red[1024];
    const int tid = threadIdx.x;
    const float4* v = (const float4*)g_sq;        // 8192 float4 total
    float4 t = v[blockIdx.x * 1024 + tid];
    red[tid] = (t.x + t.y) + (t.z + t.w);
    __syncthreads();
    #pragma unroll
    for (int off = 512; off > 0; off >>= 1) {
        if (tid < off) red[tid] += red[tid + off];
        __syncthreads();
    }
    if (tid == 0) {
        g_partial[blockIdx.x] = red[0];
        __threadfence();
        if (atomicAdd(&g_rcount, 1) == 7) {       // last block finishes
            float s = 0.0f;
            volatile float* gp = g_partial;
            #pragma unroll
            for (int i = 0; i < 8; i++) s += gp[i];  // fixed order
            out[0] = s * (5.0f / (float)N_PTS);   // (mean1 + mean2)*0.5*10
            g_rcount = 0;                          // restore invariant
        }
    }
}

extern "C" void kernel_launch(void* const* d_in, const int* in_sizes, int n_in,
                              void* d_out, int out_size) {
    const float* state_x = (const float*)d_in[0];
    const float* target  = (const float*)d_in[1];

    count_kernel<<<(2 * N_PTS) / 256, 256>>>(state_x, target);
    scan_kernel<<<2, 1024>>>();
    scatter_kernel<<<(2 * N_PTS) / 256, 256>>>(state_x, target);

    dim3 sgrid((N_PTS * SUBQ) / SBLK, 2);
    search_kernel<<<sgrid, SBLK>>>();

    reduce_kernel<<<8, 1024>>>((float*)d_out);
}